// round 16
// baseline (speedup 1.0000x reference)
#include <cuda_runtime.h>
#include <cuda_bf16.h>
#include <cstdint>

typedef unsigned long long u64;

// Problem: b=4, h=8, L=8192, dk=dv=64, chunk=32. 32 chains x 256 chunks.
#define G_CHUNKS 8192
#define O_ELEMS  16777216   // 4*8*8192*64

// ---------------- scratch (device globals; allocation-free rule) -----------
__device__ float4 g_qn4[G_CHUNKS * 512];   // qn  [g][32][64] row-major
__device__ float4 g_w4 [G_CHUNKS * 512];   // -w  [g][d4(16)][i(32)] (NEGATED, transposed)
__device__ float4 g_kT4[G_CHUNKS * 512];   // k^T [g][64][32]
__device__ float4 g_uB4[G_CHUNKS * 512];   // u0  [g][split(4)][c4(4)][i(32)]
__device__ float4 g_Lc4[G_CHUNKS * 256];   // Lc  [g][32][32] (tril incl diag)
__device__ unsigned g_flag[G_CHUNKS * 4];  // ready flags, one per (chunk, split)

// ---------------- f32x2 / LDS helpers --------------------------------------
__device__ __forceinline__ u64 fma2(u64 a, u64 b, u64 c) {
    u64 d; asm("fma.rn.f32x2 %0, %1, %2, %3;" : "=l"(d) : "l"(a), "l"(b), "l"(c)); return d;
}
__device__ __forceinline__ u64 mul2(u64 a, u64 b) {
    u64 d; asm("mul.rn.f32x2 %0, %1, %2;" : "=l"(d) : "l"(a), "l"(b)); return d;
}
__device__ __forceinline__ u64 pack2(float x, float y) {
    u64 d; asm("mov.b64 %0, {%1, %2};" : "=l"(d) : "f"(x), "f"(y)); return d;
}
__device__ __forceinline__ float2 unpack2(u64 a) {
    float2 r; asm("mov.b64 {%0, %1}, %2;" : "=f"(r.x), "=f"(r.y) : "l"(a)); return r;
}
__device__ __forceinline__ float hadd2(u64 a) {
    float2 r = unpack2(a); return r.x + r.y;
}
__device__ __forceinline__ void ldsv2(u64& a, u64& b, uint32_t addr) {
    asm volatile("ld.shared.v2.u64 {%0, %1}, [%2];" : "=l"(a), "=l"(b) : "r"(addr));
}
__device__ __forceinline__ void sts_f32(uint32_t addr, float v) {
    asm volatile("st.shared.f32 [%0], %1;" :: "r"(addr), "f"(v));
}
__device__ __forceinline__ void sts_v4(uint32_t addr, float4 v) {
    asm volatile("st.shared.v4.f32 [%0], {%1,%2,%3,%4};"
                 :: "r"(addr), "f"(v.x), "f"(v.y), "f"(v.z), "f"(v.w));
}
__device__ __forceinline__ uint32_t s2u(const void* p) {
    return (uint32_t)__cvta_generic_to_shared(p);
}
__device__ __forceinline__ unsigned ld_acq(const unsigned* p) {
    unsigned v;
    asm volatile("ld.acquire.gpu.global.u32 %0, [%1];" : "=r"(v) : "l"(p) : "memory");
    return v;
}

// Phase2 smem layout (shrunk u0 stride so 3 blocks/SM fit)
#define P2_QD    0          // q  rows: 32 x 272B
#define P2_WD    8704       // -w rows: 32 x 272B
#define P2_KT    17408      // kT rows: 64 x 144B
#define P2_LC    26624      // Lc rows: 32 x 144B
#define P2_U0    31232      // u0 rows: 32 x 80B (64B used)
#define P2_BUF   33792
#define P2_MS    67584      // S mirror: 4 warps x 1KB
#define P2_UL    71680      // u local : 4 warps x 512B
#define P2_SMEM  73728

// ===========================================================================
// FUSED kernel. Blocks 0..127: phase2 (scan). Blocks 128..8319: phase1,
// t-major chunk order (g = bh*256 + t, linear = t*32 + bh).
// ===========================================================================
__global__ void __launch_bounds__(256, 3) dn_fused(
    const float* __restrict__ q, const float* __restrict__ k,
    const float* __restrict__ v, const float* __restrict__ beta,
    float* __restrict__ out, int wantS)
{
    extern __shared__ float smem[];
    const uint32_t sb = s2u(smem);
    const int tid  = threadIdx.x;
    const int lane = tid & 31;
    const int wp   = tid >> 5;

    if (blockIdx.x >= 128) {
        // ==================== PHASE 1 ROLE ==================================
        const int gl = blockIdx.x - 128;
        const int tt = gl >> 5, bh1 = gl & 31;
        const size_t g = (size_t)bh1 * 256 + tt;

        float* sQ    = smem;           // 32 x 68
        float* sK    = smem + 2176;    // 32 x 68
        float* sV    = smem + 4352;    // 32 x 68
        float* sA    = smem + 6528;    // 32 x 33
        float* sRinv = smem + 7584;    // 64
        float* sBeta = smem + 7648;    // 32
        const uint32_t aQ = sb, aK = sb + 8704u, aV = sb + 17408u;

        // ---- stage 1: load raw q,k,v + beta --------------------------------
        const float4* qb = (const float4*)(q + g * 2048);
        const float4* kb = (const float4*)(k + g * 2048);
        const float4* vb = (const float4*)(v + g * 2048);
#pragma unroll
        for (int it = 0; it < 2; ++it) {
            int f  = tid + it * 256;
            int so = (f >> 4) * 68 + ((f & 15) << 2);
            *(float4*)&sQ[so] = qb[f];
            *(float4*)&sK[so] = kb[f];
            *(float4*)&sV[so] = vb[f];
        }
        if (tid < 32) sBeta[tid] = beta[g * 32 + tid];
        __syncthreads();                               // B1

        // ---- stage 2a: rsqrt factors ---------------------------------------
        {
            int r = tid >> 2, qd = tid & 3;
            const float4* rp = (const float4*)(((r < 32) ? (sQ + r * 68)
                                                         : (sK + (r - 32) * 68)) + qd * 16);
            float s = 0.f;
#pragma unroll
            for (int m = 0; m < 4; ++m) {
                float4 a = rp[m];
                s = fmaf(a.x, a.x, s); s = fmaf(a.y, a.y, s);
                s = fmaf(a.z, a.z, s); s = fmaf(a.w, a.w, s);
            }
            s += __shfl_xor_sync(0xffffffffu, s, 1);
            s += __shfl_xor_sync(0xffffffffu, s, 2);
            if (qd == 0) sRinv[r] = rsqrtf(s + 1e-6f);
        }

        // ---- stage 2b: RAW dots, fused single pass -------------------------
        const int i0 = wp * 4;
        u64 a2A[4] = {0, 0, 0, 0}, a2L[4] = {0, 0, 0, 0};
#pragma unroll 4
        for (int dd = 0; dd < 16; ++dd) {
            u64 kj0, kj1;
            ldsv2(kj0, kj1, aK + (uint32_t)(lane * 272 + dd * 16));
#pragma unroll
            for (int e = 0; e < 4; ++e) {
                u64 ki0, ki1, qi0, qi1;
                ldsv2(ki0, ki1, aK + (uint32_t)((i0 + e) * 272 + dd * 16));
                ldsv2(qi0, qi1, aQ + (uint32_t)((i0 + e) * 272 + dd * 16));
                a2A[e] = fma2(ki0, kj0, a2A[e]);  a2A[e] = fma2(ki1, kj1, a2A[e]);
                a2L[e] = fma2(qi0, kj0, a2L[e]);  a2L[e] = fma2(qi1, kj1, a2L[e]);
            }
        }
        __syncthreads();                               // B2

        // ---- stage 3: scale, write A + Lc; normalize sK --------------------
        {
            float* g_Lc = (float*)g_Lc4 + g * 1024;
            float rkj = sRinv[32 + lane];
#pragma unroll
            for (int e = 0; e < 4; ++e) {
                int i = i0 + e;
                float scA = sBeta[i] * sRinv[32 + i] * rkj;
                float scL = sRinv[i] * rkj;
                sA[i * 33 + lane]   = (lane <  i) ? (-scA * hadd2(a2A[e])) : 0.0f;
                g_Lc[i * 32 + lane] = (lane <= i) ? ( scL * hadd2(a2L[e])) : 0.0f;
            }
            for (int e = tid; e < 2048; e += 256) {
                int r = e >> 6, d = e & 63;
                sK[r * 68 + d] *= sRinv[32 + r];
            }
        }
        __syncthreads();                               // B3

        // ---- stage 4: warp0 trisolve + beta-fold | others drain qn,kT -------
        if (wp == 0) {
#pragma unroll
            for (int i = 1; i < 32; ++i) {
                float r = sA[i * 33 + lane];
                float v0 = r, v1 = 0.f, v2 = 0.f, v3 = 0.f;
#pragma unroll
                for (int j = 1; j < i; ++j) {
                    float aij = __shfl_sync(0xffffffffu, r, j);
                    float tj  = sA[j * 33 + lane];
                    if ((j & 3) == 0)      v0 = fmaf(aij, tj, v0);
                    else if ((j & 3) == 1) v1 = fmaf(aij, tj, v1);
                    else if ((j & 3) == 2) v2 = fmaf(aij, tj, v2);
                    else                   v3 = fmaf(aij, tj, v3);
                }
                sA[i * 33 + lane] = (v0 + v1) + (v2 + v3);
            }
            float bj = sBeta[lane];
#pragma unroll
            for (int i = 1; i < 32; ++i)
                sA[i * 33 + lane] *= bj;
        } else {
            float* g_qn = (float*)g_qn4 + g * 2048;
            float* g_kT = (float*)g_kT4 + g * 2048;
            for (int e = (wp - 1) * 32 + lane; e < 4096; e += 224) {
                if (e < 2048) {
                    int r = e >> 6, d = e & 63;
                    g_qn[e] = sQ[r * 68 + d] * sRinv[r];
                } else {
                    int f = e - 2048;
                    int d = f >> 5, i = f & 31;
                    g_kT[f] = sK[i * 68 + d];
                }
            }
        }
        __syncthreads();                               // B4

        // ---- stage 5: fused u/w (one j-loop, 8 f32x2 accumulators) ----------
        {
            const int db = wp * 4;
            const uint32_t oc0 = (uint32_t)(db * 4);
            const uint32_t oc1 = (uint32_t)((db + 32) * 4);
            float bi = sBeta[lane];
            u64 b2 = pack2(bi, bi);

            u64 xa, xb;
            ldsv2(xa, xb, aV + (uint32_t)(lane * 272) + oc0);
            u64 u0a = mul2(b2, xa), u0b = mul2(b2, xb);
            ldsv2(xa, xb, aV + (uint32_t)(lane * 272) + oc1);
            u64 u1a = mul2(b2, xa), u1b = mul2(b2, xb);
            ldsv2(xa, xb, aK + (uint32_t)(lane * 272) + oc0);
            u64 w0a = mul2(b2, xa), w0b = mul2(b2, xb);
            ldsv2(xa, xb, aK + (uint32_t)(lane * 272) + oc1);
            u64 w1a = mul2(b2, xa), w1b = mul2(b2, xb);

#pragma unroll 2
            for (int j = 0; j < 32; ++j) {
                float t = sA[lane * 33 + j];
                u64 t2 = pack2(t, t);
                uint32_t rowj = (uint32_t)(j * 272);
                ldsv2(xa, xb, aV + rowj + oc0);
                u0a = fma2(t2, xa, u0a);  u0b = fma2(t2, xb, u0b);
                ldsv2(xa, xb, aV + rowj + oc1);
                u1a = fma2(t2, xa, u1a);  u1b = fma2(t2, xb, u1b);
                ldsv2(xa, xb, aK + rowj + oc0);
                w0a = fma2(t2, xa, w0a);  w0b = fma2(t2, xb, w0b);
                ldsv2(xa, xb, aK + rowj + oc1);
                w1a = fma2(t2, xa, w1a);  w1b = fma2(t2, xb, w1b);
            }

            float2 p0, p1;
            p0 = unpack2(u0a); p1 = unpack2(u0b);
            g_uB4[g * 512 + (size_t)(db >> 4) * 128 + (size_t)((db & 15) >> 2) * 32 + lane] =
                make_float4(p0.x, p0.y, p1.x, p1.y);
            p0 = unpack2(u1a); p1 = unpack2(u1b);
            g_uB4[g * 512 + (size_t)((db + 32) >> 4) * 128 + (size_t)(((db + 32) & 15) >> 2) * 32 + lane] =
                make_float4(p0.x, p0.y, p1.x, p1.y);
            p0 = unpack2(w0a); p1 = unpack2(w0b);
            g_w4[g * 512 + (size_t)wp * 32 + lane] =
                make_float4(-p0.x, -p0.y, -p1.x, -p1.y);
            p0 = unpack2(w1a); p1 = unpack2(w1b);
            g_w4[g * 512 + (size_t)(wp + 8) * 32 + lane] =
                make_float4(-p0.x, -p0.y, -p1.x, -p1.y);
        }

        // ---- publish: all chunk data visible, then set 4 split flags --------
        __syncthreads();
        if (tid == 0) {
            __threadfence();
            unsigned* fp = g_flag + g * 4;
            fp[0] = 1u; fp[1] = 1u; fp[2] = 1u; fp[3] = 1u;
        }
        return;
    }

    // ======================= PHASE 2 ROLE ===================================
    const int bh = blockIdx.x >> 2;
    const int sp = blockIdx.x & 3;
    const size_t gbase = (size_t)bh * 256;

    if (wp >= 4) {
        // =================== STAGING WARPS (4-7) =============================
        const int st = tid - 128;          // 0..127
        float4 rq[4], rw[4], rt[4], rl[2], ru;

#define P2_POLL(T) do {                                                        \
    const unsigned* fp_ = g_flag + ((gbase + (size_t)(T)) * 4 + sp);           \
    while (ld_acq(fp_) == 0) { }                                               \
} while (0)

#define P2_LOADS(T) do {                                                       \
    size_t g_ = gbase + (size_t)(T);                                           \
    rq[0] = g_qn4[g_ * 512 + st];        rq[1] = g_qn4[g_ * 512 + st + 128];   \
    rq[2] = g_qn4[g_ * 512 + st + 256];  rq[3] = g_qn4[g_ * 512 + st + 384];   \
    rw[0] = g_w4 [g_ * 512 + st];        rw[1] = g_w4 [g_ * 512 + st + 128];   \
    rw[2] = g_w4 [g_ * 512 + st + 256];  rw[3] = g_w4 [g_ * 512 + st + 384];   \
    rt[0] = g_kT4[g_ * 512 + st];        rt[1] = g_kT4[g_ * 512 + st + 128];   \
    rt[2] = g_kT4[g_ * 512 + st + 256];  rt[3] = g_kT4[g_ * 512 + st + 384];   \
    rl[0] = g_Lc4[g_ * 256 + st];        rl[1] = g_Lc4[g_ * 256 + st + 128];   \
    ru    = g_uB4[g_ * 512 + (size_t)sp * 128 + st];                           \
} while (0)

#define P2_STORES(BUF) do {                                                    \
    uint32_t bb = sb + (uint32_t)(BUF) * P2_BUF;                               \
    _Pragma("unroll")                                                          \
    for (int m = 0; m < 4; ++m) {                                              \
        int f = st + m * 128;                                                  \
        sts_v4(bb + P2_QD + (uint32_t)((f >> 4) * 272 + (f & 15) * 16), rq[m]);\
        sts_v4(bb + P2_WD + (uint32_t)((f & 31) * 272 + (f >> 5) * 16), rw[m]);\
        sts_v4(bb + P2_KT + (uint32_t)((f >> 3) * 144 + (f & 7)  * 16), rt[m]);\
    }                                                                          \
    _Pragma("unroll")                                                          \
    for (int m = 0; m < 2; ++m) {                                              \
        int f = st + m * 128;                                                  \
        sts_v4(bb + P2_LC + (uint32_t)((f >> 3) * 144 + (f & 7)  * 16), rl[m]);\
    }                                                                          \
    sts_v4(bb + P2_U0 + (uint32_t)((st & 31) * 80 + (st >> 5) * 16), ru);      \
} while (0)

        P2_POLL(0);  P2_LOADS(0);
        P2_STORES(0);
        P2_POLL(1);  P2_LOADS(1);
        __syncthreads();
        for (int t = 0; t < 256; ++t) {
            if (t + 1 < 256) P2_STORES((t + 1) & 1);
            if (t + 2 < 256) { P2_POLL(t + 2); P2_LOADS(t + 2); }
            // reset consumed flags (all staging warps passed their polls at
            // least one barrier ago): chunk 0&1 at t==0, chunk t+1 at t>=1.
            if (wp == 4 && lane == 0) {
                if (t == 0) {
                    g_flag[(gbase + 0) * 4 + sp] = 0u;
                    g_flag[(gbase + 1) * 4 + sp] = 0u;
                } else if (t + 1 < 256) {
                    g_flag[(gbase + (size_t)t + 1) * 4 + sp] = 0u;
                }
            }
            __syncthreads();
        }
        return;
#undef P2_POLL
#undef P2_LOADS
#undef P2_STORES
    }

    // ====================== COMPUTE WARPS (0-3) =============================
    const int c0 = sp * 16 + wp * 4;
    const uint32_t msb = sb + P2_MS + (uint32_t)wp * 1024;   // S mirror, col-major
    const uint32_t ulb = sb + P2_UL + (uint32_t)wp * 512;    // u local, col-major

#pragma unroll
    for (int c = 0; c < 4; ++c) {
        sts_f32(msb + (uint32_t)c * 256 + (uint32_t)lane * 4, 0.f);
        sts_f32(msb + (uint32_t)c * 256 + (uint32_t)(lane + 32) * 4, 0.f);
    }
    float S0[4] = {0.f, 0.f, 0.f, 0.f};
    float S1[4] = {0.f, 0.f, 0.f, 0.f};

    __syncthreads();   // matches staging warps' first barrier

    for (int t = 0; t < 256; ++t) {
        const uint32_t bb = sb + (uint32_t)(t & 1) * P2_BUF;

        const uint32_t wrow = bb + P2_WD + (uint32_t)lane * 272;
        const uint32_t qrow = bb + P2_QD + (uint32_t)lane * 272;
        u64 au[4] = {0, 0, 0, 0}, ao[4] = {0, 0, 0, 0};
#pragma unroll
        for (int i = 0; i < 16; ++i) {
            u64 w01, w23, q01, q23;
            ldsv2(w01, w23, wrow + (uint32_t)i * 16);
            ldsv2(q01, q23, qrow + (uint32_t)i * 16);
#pragma unroll
            for (int c = 0; c < 4; ++c) {
                u64 sa, sbv;
                ldsv2(sa, sbv, msb + (uint32_t)c * 256 + (uint32_t)i * 16);
                au[c] = fma2(w01, sa, au[c]);  au[c] = fma2(w23, sbv, au[c]);
                ao[c] = fma2(q01, sa, ao[c]);  ao[c] = fma2(q23, sbv, ao[c]);
            }
        }
        u64 ua, ub;
        ldsv2(ua, ub, bb + P2_U0 + (uint32_t)lane * 80 + (uint32_t)wp * 16);
        float2 u01 = unpack2(ua), u23 = unpack2(ub);
        float uu[4];
        uu[0] = u01.x + hadd2(au[0]);  uu[1] = u01.y + hadd2(au[1]);
        uu[2] = u23.x + hadd2(au[2]);  uu[3] = u23.y + hadd2(au[3]);

#pragma unroll
        for (int c = 0; c < 4; ++c)
            sts_f32(ulb + (uint32_t)c * 128 + (uint32_t)lane * 4, uu[c]);
        __syncwarp();

        const uint32_t lrow  = bb + P2_LC + (uint32_t)lane * 144;
        const uint32_t krow0 = bb + P2_KT + (uint32_t)lane * 144;
        const uint32_t krow1 = bb + P2_KT + (uint32_t)(lane + 32) * 144;
        u64 aoL[4] = {0, 0, 0, 0}, d0[4] = {0, 0, 0, 0}, d1[4] = {0, 0, 0, 0};
#pragma unroll
        for (int j4 = 0; j4 < 8; ++j4) {
            u64 L01, L23, k0a, k0b, k1a, k1b;
            ldsv2(L01, L23, lrow  + (uint32_t)j4 * 16);
            ldsv2(k0a, k0b, krow0 + (uint32_t)j4 * 16);
            ldsv2(k1a, k1b, krow1 + (uint32_t)j4 * 16);
#pragma unroll
            for (int c = 0; c < 4; ++c) {
                u64 up01, up23;
                ldsv2(up01, up23, ulb + (uint32_t)c * 128 + (uint32_t)j4 * 16);
                aoL[c] = fma2(L01, up01, aoL[c]);  aoL[c] = fma2(L23, up23, aoL[c]);
                d0[c]  = fma2(k0a, up01, d0[c]);   d0[c]  = fma2(k0b, up23, d0[c]);
                d1[c]  = fma2(k1a, up01, d1[c]);   d1[c]  = fma2(k1b, up23, d1[c]);
            }
        }

        float o[4];
#pragma unroll
        for (int c = 0; c < 4; ++c) {
            S0[c] += hadd2(d0[c]);
            S1[c] += hadd2(d1[c]);
            o[c] = hadd2(ao[c]) + hadd2(aoL[c]);
            sts_f32(msb + (uint32_t)c * 256 + (uint32_t)lane * 4, S0[c]);
            sts_f32(msb + (uint32_t)c * 256 + (uint32_t)(lane + 32) * 4, S1[c]);
        }

        size_t orow = ((size_t)bh * 8192 + (size_t)t * 32 + lane) * 64 + c0;
        *(float4*)(out + orow) = make_float4(o[0], o[1], o[2], o[3]);

        __syncthreads();
    }

    if (wantS) {
        size_t so = (size_t)O_ELEMS + (size_t)bh * 4096 + (size_t)lane * 64 + c0;
        *(float4*)(out + so)        = make_float4(S0[0], S0[1], S0[2], S0[3]);
        *(float4*)(out + so + 2048) = make_float4(S1[0], S1[1], S1[2], S1[3]);
    }
}

// ===========================================================================
extern "C" void kernel_launch(void* const* d_in, const int* in_sizes, int n_in,
                              void* d_out, int out_size)
{
    const float* q    = (const float*)d_in[0];
    const float* k    = (const float*)d_in[1];
    const float* v    = (const float*)d_in[2];
    const float* beta = (const float*)d_in[3];
    float* out = (float*)d_out;
    int wantS = (out_size > O_ELEMS) ? 1 : 0;

    cudaFuncSetAttribute(dn_fused, cudaFuncAttributeMaxDynamicSharedMemorySize, P2_SMEM);
    cudaFuncSetAttribute(dn_fused, cudaFuncAttributePreferredSharedMemoryCarveout, 100);

    dn_fused<<<128 + G_CHUNKS, 256, P2_SMEM>>>(q, k, v, beta, out, wantS);
}

// round 17
// speedup vs baseline: 1.3974x; 1.3974x over previous
#include <cuda_runtime.h>
#include <cuda_bf16.h>
#include <cstdint>

typedef unsigned long long u64;

// Problem: b=4, h=8, L=8192, dk=dv=64, chunk=32. 32 chains x 256 chunks.
#define G_CHUNKS 8192
#define O_ELEMS  16777216   // 4*8*8192*64

// ---------------- scratch (device globals; allocation-free rule) -----------
__device__ float4 g_qn4[G_CHUNKS * 512];   // qn  [g][32][64] row-major
__device__ float4 g_w4 [G_CHUNKS * 512];   // -w  [g][d4(16)][i(32)] (NEGATED, transposed)
__device__ float4 g_kT4[G_CHUNKS * 512];   // k^T [g][64][32]
__device__ float4 g_uB4[G_CHUNKS * 512];   // u0  [g][split(4)][c4(4)][i(32)]
__device__ float4 g_Lc4[G_CHUNKS * 256];   // Lc  [g][32][32] (tril incl diag)

// ---------------- f32x2 / LDS helpers --------------------------------------
__device__ __forceinline__ u64 fma2(u64 a, u64 b, u64 c) {
    u64 d; asm("fma.rn.f32x2 %0, %1, %2, %3;" : "=l"(d) : "l"(a), "l"(b), "l"(c)); return d;
}
__device__ __forceinline__ u64 mul2(u64 a, u64 b) {
    u64 d; asm("mul.rn.f32x2 %0, %1, %2;" : "=l"(d) : "l"(a), "l"(b)); return d;
}
__device__ __forceinline__ u64 pack2(float x, float y) {
    u64 d; asm("mov.b64 %0, {%1, %2};" : "=l"(d) : "f"(x), "f"(y)); return d;
}
__device__ __forceinline__ float2 unpack2(u64 a) {
    float2 r; asm("mov.b64 {%0, %1}, %2;" : "=f"(r.x), "=f"(r.y) : "l"(a)); return r;
}
__device__ __forceinline__ float hadd2(u64 a) {
    float2 r = unpack2(a); return r.x + r.y;
}
__device__ __forceinline__ void ldsv2(u64& a, u64& b, uint32_t addr) {
    asm volatile("ld.shared.v2.u64 {%0, %1}, [%2];" : "=l"(a), "=l"(b) : "r"(addr));
}
__device__ __forceinline__ void sts_f32(uint32_t addr, float v) {
    asm volatile("st.shared.f32 [%0], %1;" :: "r"(addr), "f"(v));
}
__device__ __forceinline__ void sts_v4(uint32_t addr, float4 v) {
    asm volatile("st.shared.v4.f32 [%0], {%1,%2,%3,%4};"
                 :: "r"(addr), "f"(v.x), "f"(v.y), "f"(v.z), "f"(v.w));
}
__device__ __forceinline__ uint32_t s2u(const void* p) {
    return (uint32_t)__cvta_generic_to_shared(p);
}

// ===========================================================================
// Phase 1 (R15): fused dot pass; sK normalized in place; beta folded into T
// columns by warp 0; stage5 fused across all 4 column groups (one j-loop,
// single sA read per j, 4 broadcast ldsv2 per j, 8 f32x2 accumulators).
// ===========================================================================
__global__ void __launch_bounds__(256, 3) dn_phase1(
    const float* __restrict__ q, const float* __restrict__ k,
    const float* __restrict__ v, const float* __restrict__ beta)
{
    __shared__ float sQ[32 * 68], sK[32 * 68], sV[32 * 68];   // q,k raw -> k normalized
    __shared__ float sA[32 * 33];
    __shared__ float sRinv[64];        // [0:32) q rows, [32:64) k rows
    __shared__ float sBeta[32];

    const int tid  = threadIdx.x;
    const int lane = tid & 31;
    const int wp   = tid >> 5;
    const size_t g = blockIdx.x;

    const uint32_t aQ = s2u(sQ), aK = s2u(sK), aV = s2u(sV);

    // ---- stage 1: load q,k,v (raw) + beta ------------------------------------
    const float4* qb = (const float4*)(q + g * 2048);
    const float4* kb = (const float4*)(k + g * 2048);
    const float4* vb = (const float4*)(v + g * 2048);
#pragma unroll
    for (int it = 0; it < 2; ++it) {
        int f  = tid + it * 256;
        int so = (f >> 4) * 68 + ((f & 15) << 2);
        *(float4*)&sQ[so] = qb[f];
        *(float4*)&sK[so] = kb[f];
        *(float4*)&sV[so] = vb[f];
    }
    if (tid < 32) sBeta[tid] = beta[g * 32 + tid];
    __syncthreads();                                   // B1

    // ---- stage 2a: rsqrt factors, 256 threads (4 per row) ---------------------
    {
        int r = tid >> 2, qd = tid & 3;
        const float4* rp = (const float4*)(((r < 32) ? (sQ + r * 68)
                                                     : (sK + (r - 32) * 68)) + qd * 16);
        float s = 0.f;
#pragma unroll
        for (int m = 0; m < 4; ++m) {
            float4 a = rp[m];
            s = fmaf(a.x, a.x, s); s = fmaf(a.y, a.y, s);
            s = fmaf(a.z, a.z, s); s = fmaf(a.w, a.w, s);
        }
        s += __shfl_xor_sync(0xffffffffu, s, 1);
        s += __shfl_xor_sync(0xffffffffu, s, 2);
        if (qd == 0) sRinv[r] = rsqrtf(s + 1e-6f);
    }

    // ---- stage 2b: RAW dots, FUSED single pass (kj shared by A and L) --------
    const int i0 = wp * 4;
    u64 a2A[4] = {0, 0, 0, 0}, a2L[4] = {0, 0, 0, 0};
#pragma unroll 4
    for (int dd = 0; dd < 16; ++dd) {
        u64 kj0, kj1;
        ldsv2(kj0, kj1, aK + (uint32_t)(lane * 272 + dd * 16));
#pragma unroll
        for (int e = 0; e < 4; ++e) {
            u64 ki0, ki1, qi0, qi1;
            ldsv2(ki0, ki1, aK + (uint32_t)((i0 + e) * 272 + dd * 16));  // broadcast
            ldsv2(qi0, qi1, aQ + (uint32_t)((i0 + e) * 272 + dd * 16));  // broadcast
            a2A[e] = fma2(ki0, kj0, a2A[e]);  a2A[e] = fma2(ki1, kj1, a2A[e]);
            a2L[e] = fma2(qi0, kj0, a2L[e]);  a2L[e] = fma2(qi1, kj1, a2L[e]);
        }
    }
    __syncthreads();                                   // B2 (sRinv visible, dots done)

    // ---- stage 3: scale + write A and Lc; normalize sK in place ---------------
    {
        float* g_Lc = (float*)g_Lc4 + g * 1024;
        float rkj = sRinv[32 + lane];
#pragma unroll
        for (int e = 0; e < 4; ++e) {
            int i = i0 + e;
            float scA = sBeta[i] * sRinv[32 + i] * rkj;   // beta_i rinvk_i rinvk_j
            float scL = sRinv[i] * rkj;                   // rinvq_i rinvk_j
            sA[i * 33 + lane]   = (lane <  i) ? (-scA * hadd2(a2A[e])) : 0.0f;
            g_Lc[i * 32 + lane] = (lane <= i) ? ( scL * hadd2(a2L[e])) : 0.0f;
        }
        // normalize sK rows (raw dots already consumed)
        for (int e = tid; e < 2048; e += 256) {
            int r = e >> 6, d = e & 63;
            sK[r * 68 + d] *= sRinv[32 + r];
        }
    }
    __syncthreads();                                   // B3

    // ---- stage 4: warp 0 trisolve + beta-fold | warps 1-7 drain qn,kT ---------
    if (wp == 0) {
        // T = (I-A)^{-1} - I in place; rows strict-lower so no predicate/sync.
#pragma unroll
        for (int i = 1; i < 32; ++i) {
            float r = sA[i * 33 + lane];
            float v0 = r, v1 = 0.f, v2 = 0.f, v3 = 0.f;
#pragma unroll
            for (int j = 1; j < i; ++j) {
                float aij = __shfl_sync(0xffffffffu, r, j);
                float tj  = sA[j * 33 + lane];
                if ((j & 3) == 0)      v0 = fmaf(aij, tj, v0);
                else if ((j & 3) == 1) v1 = fmaf(aij, tj, v1);
                else if ((j & 3) == 2) v2 = fmaf(aij, tj, v2);
                else                   v3 = fmaf(aij, tj, v3);
            }
            sA[i * 33 + lane] = (v0 + v1) + (v2 + v3);
        }
        // fold beta into T columns: T'[i][j] = T[i][j] * beta[j]
        float bj = sBeta[lane];
#pragma unroll
        for (int i = 1; i < 32; ++i)
            sA[i * 33 + lane] *= bj;
    } else {
        float* g_qn = (float*)g_qn4 + g * 2048;
        float* g_kT = (float*)g_kT4 + g * 2048;
        for (int e = (wp - 1) * 32 + lane; e < 4096; e += 224) {
            if (e < 2048) {
                int r = e >> 6, d = e & 63;
                g_qn[e] = sQ[r * 68 + d] * sRinv[r];
            } else {
                int f = e - 2048;
                int d = f >> 5, i = f & 31;
                g_kT[f] = sK[i * 68 + d];            // sK already normalized
            }
        }
    }
    __syncthreads();                                   // B4

    // ---- stage 5 (R15): fused u/w across 4 col-groups, single j-loop ----------
    {
        const int db = wp * 4;                 // this warp's column base (0..28)
        const uint32_t oc0 = (uint32_t)(db * 4);          // byte offset cols db
        const uint32_t oc1 = (uint32_t)((db + 32) * 4);   // byte offset cols db+32
        float bi = sBeta[lane];
        u64 b2 = pack2(bi, bi);

        u64 xa, xb;
        ldsv2(xa, xb, aV + (uint32_t)(lane * 272) + oc0);
        u64 u0a = mul2(b2, xa), u0b = mul2(b2, xb);
        ldsv2(xa, xb, aV + (uint32_t)(lane * 272) + oc1);
        u64 u1a = mul2(b2, xa), u1b = mul2(b2, xb);
        ldsv2(xa, xb, aK + (uint32_t)(lane * 272) + oc0);
        u64 w0a = mul2(b2, xa), w0b = mul2(b2, xb);
        ldsv2(xa, xb, aK + (uint32_t)(lane * 272) + oc1);
        u64 w1a = mul2(b2, xa), w1b = mul2(b2, xb);

#pragma unroll 2
        for (int j = 0; j < 32; ++j) {
            float t = sA[lane * 33 + j];              // zero for j >= lane
            u64 t2 = pack2(t, t);
            uint32_t rowj = (uint32_t)(j * 272);
            ldsv2(xa, xb, aV + rowj + oc0);           // broadcast
            u0a = fma2(t2, xa, u0a);  u0b = fma2(t2, xb, u0b);
            ldsv2(xa, xb, aV + rowj + oc1);           // broadcast
            u1a = fma2(t2, xa, u1a);  u1b = fma2(t2, xb, u1b);
            ldsv2(xa, xb, aK + rowj + oc0);           // broadcast
            w0a = fma2(t2, xa, w0a);  w0b = fma2(t2, xb, w0b);
            ldsv2(xa, xb, aK + rowj + oc1);           // broadcast
            w1a = fma2(t2, xa, w1a);  w1b = fma2(t2, xb, w1b);
        }

        // stores (coalesced layouts)
        float2 p0, p1;
        p0 = unpack2(u0a); p1 = unpack2(u0b);
        g_uB4[g * 512 + (size_t)(db >> 4) * 128 + (size_t)((db & 15) >> 2) * 32 + lane] =
            make_float4(p0.x, p0.y, p1.x, p1.y);
        p0 = unpack2(u1a); p1 = unpack2(u1b);
        g_uB4[g * 512 + (size_t)((db + 32) >> 4) * 128 + (size_t)(((db + 32) & 15) >> 2) * 32 + lane] =
            make_float4(p0.x, p0.y, p1.x, p1.y);
        p0 = unpack2(w0a); p1 = unpack2(w0b);
        g_w4[g * 512 + (size_t)wp * 32 + lane] =
            make_float4(-p0.x, -p0.y, -p1.x, -p1.y);
        p0 = unpack2(w1a); p1 = unpack2(w1b);
        g_w4[g * 512 + (size_t)(wp + 8) * 32 + lane] =
            make_float4(-p0.x, -p0.y, -p1.x, -p1.y);
    }
}

// ===========================================================================
// Phase 2: sequential scan, warp-specialized, 256 threads/block.
// (UNCHANGED from R8/R10/R12/R15: ~328 us)
// ===========================================================================
#define P2_QD    0          // q  rows: 32 x 272B
#define P2_WD    8704       // -w rows: 32 x 272B
#define P2_KT    17408      // kT rows: 64 x 144B
#define P2_LC    26624      // Lc rows: 32 x 144B
#define P2_U0    31232      // u0 rows: 32 x 144B (only 64B used per row)
#define P2_BUF   35840
#define P2_MS    71680      // S mirror: 4 warps x (4 cols x 64 floats) = 4KB
#define P2_UL    75776      // u local : 4 warps x (4 cols x 32 floats) = 2KB
#define P2_SMEM  77824

__global__ void __launch_bounds__(256) dn_phase2(float* __restrict__ out, int wantS)
{
    extern __shared__ float smem[];
    const uint32_t sb = s2u(smem);

    const int tid  = threadIdx.x;
    const int lane = tid & 31;
    const int wp   = tid >> 5;
    const int bh   = blockIdx.x >> 2;
    const int sp   = blockIdx.x & 3;
    const size_t gbase = (size_t)bh * 256;

    if (wp >= 4) {
        // =================== STAGING ROLE (warps 4-7) ========================
        const int st = tid - 128;          // 0..127
        float4 rq[4], rw[4], rt[4], rl[2], ru;

#define P2_LOADS(T) do {                                                       \
    size_t g_ = gbase + (size_t)(T);                                           \
    rq[0] = g_qn4[g_ * 512 + st];        rq[1] = g_qn4[g_ * 512 + st + 128];   \
    rq[2] = g_qn4[g_ * 512 + st + 256];  rq[3] = g_qn4[g_ * 512 + st + 384];   \
    rw[0] = g_w4 [g_ * 512 + st];        rw[1] = g_w4 [g_ * 512 + st + 128];   \
    rw[2] = g_w4 [g_ * 512 + st + 256];  rw[3] = g_w4 [g_ * 512 + st + 384];   \
    rt[0] = g_kT4[g_ * 512 + st];        rt[1] = g_kT4[g_ * 512 + st + 128];   \
    rt[2] = g_kT4[g_ * 512 + st + 256];  rt[3] = g_kT4[g_ * 512 + st + 384];   \
    rl[0] = g_Lc4[g_ * 256 + st];        rl[1] = g_Lc4[g_ * 256 + st + 128];   \
    ru    = g_uB4[g_ * 512 + (size_t)sp * 128 + st];                           \
} while (0)

#define P2_STORES(BUF) do {                                                    \
    uint32_t bb = sb + (uint32_t)(BUF) * P2_BUF;                               \
    _Pragma("unroll")                                                          \
    for (int m = 0; m < 4; ++m) {                                              \
        int f = st + m * 128;                                                  \
        sts_v4(bb + P2_QD + (uint32_t)((f >> 4) * 272 + (f & 15) * 16), rq[m]);\
        sts_v4(bb + P2_WD + (uint32_t)((f & 31) * 272 + (f >> 5) * 16), rw[m]);\
        sts_v4(bb + P2_KT + (uint32_t)((f >> 3) * 144 + (f & 7)  * 16), rt[m]);\
    }                                                                          \
    _Pragma("unroll")                                                          \
    for (int m = 0; m < 2; ++m) {                                              \
        int f = st + m * 128;                                                  \
        sts_v4(bb + P2_LC + (uint32_t)((f >> 3) * 144 + (f & 7)  * 16), rl[m]);\
    }                                                                          \
    sts_v4(bb + P2_U0 + (uint32_t)((st & 31) * 144 + (st >> 5) * 16), ru);     \
} while (0)

        P2_LOADS(0);
        P2_STORES(0);
        P2_LOADS(1);
        __syncthreads();
        for (int t = 0; t < 256; ++t) {
            if (t + 1 < 256) P2_STORES((t + 1) & 1);   // regs loaded last iter
            if (t + 2 < 256) P2_LOADS(t + 2);          // full chunk to arrive
            __syncthreads();
        }
        return;
#undef P2_LOADS
#undef P2_STORES
    }

    // ====================== COMPUTE ROLE (warps 0-3) =========================
    const int c0 = sp * 16 + wp * 4;
    const uint32_t msb = sb + P2_MS + (uint32_t)wp * 1024;   // S mirror, col-major
    const uint32_t ulb = sb + P2_UL + (uint32_t)wp * 512;    // u local, col-major

#pragma unroll
    for (int c = 0; c < 4; ++c) {
        sts_f32(msb + (uint32_t)c * 256 + (uint32_t)lane * 4, 0.f);
        sts_f32(msb + (uint32_t)c * 256 + (uint32_t)(lane + 32) * 4, 0.f);
    }
    float S0[4] = {0.f, 0.f, 0.f, 0.f};   // S[lane][c]
    float S1[4] = {0.f, 0.f, 0.f, 0.f};   // S[lane+32][c]

    __syncthreads();   // matches staging warps' first barrier

    for (int t = 0; t < 256; ++t) {
        const uint32_t bb = sb + (uint32_t)(t & 1) * P2_BUF;

        // ---- u = u0 + (-w)@S ; o = q@S  (f32x2 over d-parity, 4 cols) -------
        const uint32_t wrow = bb + P2_WD + (uint32_t)lane * 272;
        const uint32_t qrow = bb + P2_QD + (uint32_t)lane * 272;
        u64 au[4] = {0, 0, 0, 0}, ao[4] = {0, 0, 0, 0};
#pragma unroll
        for (int i = 0; i < 16; ++i) {
            u64 w01, w23, q01, q23;
            ldsv2(w01, w23, wrow + (uint32_t)i * 16);
            ldsv2(q01, q23, qrow + (uint32_t)i * 16);
#pragma unroll
            for (int c = 0; c < 4; ++c) {
                u64 sa, sbv;
                ldsv2(sa, sbv, msb + (uint32_t)c * 256 + (uint32_t)i * 16);  // broadcast
                au[c] = fma2(w01, sa, au[c]);  au[c] = fma2(w23, sbv, au[c]);
                ao[c] = fma2(q01, sa, ao[c]);  ao[c] = fma2(q23, sbv, ao[c]);
            }
        }
        u64 ua, ub;
        ldsv2(ua, ub, bb + P2_U0 + (uint32_t)lane * 144 + (uint32_t)wp * 16);
        float2 u01 = unpack2(ua), u23 = unpack2(ub);
        float uu[4];
        uu[0] = u01.x + hadd2(au[0]);  uu[1] = u01.y + hadd2(au[1]);
        uu[2] = u23.x + hadd2(au[2]);  uu[3] = u23.y + hadd2(au[3]);

        // share u within warp via col-major smem (for broadcast j-pairs)
#pragma unroll
        for (int c = 0; c < 4; ++c)
            sts_f32(ulb + (uint32_t)c * 128 + (uint32_t)lane * 4, uu[c]);
        __syncwarp();

        // ---- o += Lc@u ; dS = k^T@u  (f32x2 over j-parity) -------------------
        const uint32_t lrow  = bb + P2_LC + (uint32_t)lane * 144;
        const uint32_t krow0 = bb + P2_KT + (uint32_t)lane * 144;
        const uint32_t krow1 = bb + P2_KT + (uint32_t)(lane + 32) * 144;
        u64 aoL[4] = {0, 0, 0, 0}, d0[4] = {0, 0, 0, 0}, d1[4] = {0, 0, 0, 0};
#pragma unroll
        for (int j4 = 0; j4 < 8; ++j4) {
            u64 L01, L23, k0a, k0b, k1a, k1b;
            ldsv2(L01, L23, lrow  + (uint32_t)j4 * 16);
            ldsv2(k0a, k0b, krow0 + (uint32_t)j4 * 16);
            ldsv2(k1a, k1b, krow1 + (uint32_t)j4 * 16);
#pragma unroll
            for (int c = 0; c < 4; ++c) {
                u64 up01, up23;
                ldsv2(up01, up23, ulb + (uint32_t)c * 128 + (uint32_t)j4 * 16);  // broadcast
                aoL[c] = fma2(L01, up01, aoL[c]);  aoL[c] = fma2(L23, up23, aoL[c]);
                d0[c]  = fma2(k0a, up01, d0[c]);   d0[c]  = fma2(k0b, up23, d0[c]);
                d1[c]  = fma2(k1a, up01, d1[c]);   d1[c]  = fma2(k1b, up23, d1[c]);
            }
        }

        float o[4];
#pragma unroll
        for (int c = 0; c < 4; ++c) {
            S0[c] += hadd2(d0[c]);
            S1[c] += hadd2(d1[c]);
            o[c] = hadd2(ao[c]) + hadd2(aoL[c]);
            sts_f32(msb + (uint32_t)c * 256 + (uint32_t)lane * 4, S0[c]);
            sts_f32(msb + (uint32_t)c * 256 + (uint32_t)(lane + 32) * 4, S1[c]);
        }

        size_t orow = ((size_t)bh * 8192 + (size_t)t * 32 + lane) * 64 + c0;
        *(float4*)(out + orow) = make_float4(o[0], o[1], o[2], o[3]);

        __syncthreads();   // next buffer staged; mirror writes visible in-warp
    }

    if (wantS) {
        size_t so = (size_t)O_ELEMS + (size_t)bh * 4096 + (size_t)lane * 64 + c0;
        *(float4*)(out + so)        = make_float4(S0[0], S0[1], S0[2], S0[3]);
        *(float4*)(out + so + 2048) = make_float4(S1[0], S1[1], S1[2], S1[3]);
    }
}

// ===========================================================================
extern "C" void kernel_launch(void* const* d_in, const int* in_sizes, int n_in,
                              void* d_out, int out_size)
{
    const float* q    = (const float*)d_in[0];
    const float* k    = (const float*)d_in[1];
    const float* v    = (const float*)d_in[2];
    const float* beta = (const float*)d_in[3];
    float* out = (float*)d_out;
    int wantS = (out_size > O_ELEMS) ? 1 : 0;

    cudaFuncSetAttribute(dn_phase2, cudaFuncAttributeMaxDynamicSharedMemorySize, P2_SMEM);

    dn_phase1<<<G_CHUNKS, 256>>>(q, k, v, beta);
    dn_phase2<<<128, 256, P2_SMEM>>>(out, wantS);
}